// round 12
// baseline (speedup 1.0000x reference)
#include <cuda_runtime.h>
#include <cuda_bf16.h>
#include <cstdint>

// score[e] = dot(h[src[e]], h[dst[e]]), D=64, E=1.6M, N=100K.
//
// Strategy: bucket edges by src node (histogram + block-scan alloc + scatter),
// then warp-per-src-node gather: the src row is loaded ONCE per 8-lane group
// (f8 = 256B row in registers, via LDG.256) and reused for every edge in the
// bucket; only dst rows are gathered. Halves L2 gather traffic vs unsorted.
// Bucket placement order is nondeterministic (atomics) but each edge's score
// is computed identically -> output deterministic.

#define ROWF 64
#define NCAP 100352
#define ECAP 1605632

__device__ int  g_count[NCAP];
__device__ int  g_off[NCAP];
__device__ int  g_cursor[NCAP];
__device__ int2 g_pairs[ECAP];
__device__ int  g_total;

struct f8 { float v0, v1, v2, v3, v4, v5, v6, v7; };

__device__ __forceinline__ f8 ldg256(const float* p) {
    f8 r;
    asm volatile("ld.global.nc.v8.f32 {%0,%1,%2,%3,%4,%5,%6,%7}, [%8];"
                 : "=f"(r.v0), "=f"(r.v1), "=f"(r.v2), "=f"(r.v3),
                   "=f"(r.v4), "=f"(r.v5), "=f"(r.v6), "=f"(r.v7)
                 : "l"(p));
    return r;
}

__device__ __forceinline__ float dot8(const f8& a, const f8& b) {
    float s0 = a.v0 * b.v0 + a.v1 * b.v1;
    float s1 = a.v2 * b.v2 + a.v3 * b.v3;
    float s2 = a.v4 * b.v4 + a.v5 * b.v5;
    float s3 = a.v6 * b.v6 + a.v7 * b.v7;
    return (s0 + s1) + (s2 + s3);
}

// ---------------- prep kernels ----------------

__global__ void k_zero(int n_nodes) {
    int n = blockIdx.x * blockDim.x + threadIdx.x;
    if (n < n_nodes) g_count[n] = 0;
    if (n == 0) g_total = 0;
}

__global__ void k_hist(const int* __restrict__ src, int n_edges) {
    int e = blockIdx.x * blockDim.x + threadIdx.x;
    if (e < n_edges) atomicAdd(&g_count[src[e]], 1);
}

// Block-local exclusive scan of counts + one global atomic per block -> offsets.
__global__ void k_alloc(int n_nodes) {
    const int tid  = threadIdx.x;
    const int lane = tid & 31;
    const int wid  = tid >> 5;
    const int n = blockIdx.x * 256 + tid;

    int c = (n < n_nodes) ? g_count[n] : 0;

    // warp inclusive scan
    int x = c;
    #pragma unroll
    for (int o = 1; o < 32; o <<= 1) {
        int y = __shfl_up_sync(0xFFFFFFFFu, x, o);
        if (lane >= o) x += y;
    }

    __shared__ int wsum[8];
    __shared__ int base_s;
    if (lane == 31) wsum[wid] = x;
    __syncthreads();

    if (wid == 0) {
        int s = (lane < 8) ? wsum[lane] : 0;
        #pragma unroll
        for (int o = 1; o < 8; o <<= 1) {
            int y = __shfl_up_sync(0xFFFFFFFFu, s, o);
            if (lane >= o) s += y;
        }
        if (lane < 8) wsum[lane] = s;   // inclusive warp sums
    }
    __syncthreads();

    const int block_excl = (wid > 0) ? wsum[wid - 1] : 0;
    const int incl = block_excl + x;
    const int excl = incl - c;
    const int block_total = wsum[7];

    if (tid == 0) base_s = atomicAdd(&g_total, block_total);
    __syncthreads();

    if (n < n_nodes) {
        const int off = base_s + excl;
        g_off[n]    = off;
        g_cursor[n] = off;
    }
}

__global__ void k_scatter(const int* __restrict__ src,
                          const int* __restrict__ dst, int n_edges) {
    int e = blockIdx.x * blockDim.x + threadIdx.x;
    if (e < n_edges) {
        int s = src[e];
        int pos = atomicAdd(&g_cursor[s], 1);
        g_pairs[pos] = make_int2(dst[e], e);
    }
}

// ---------------- main gather kernel ----------------

__global__ __launch_bounds__(256)
void k_gather(const float* __restrict__ h, float* __restrict__ out, int n_nodes)
{
    const int warp = threadIdx.x >> 5;
    const int lane = threadIdx.x & 31;
    const int node = blockIdx.x * 8 + warp;
    if (node >= n_nodes) return;

    const int cnt = g_count[node];
    if (cnt == 0) return;
    const int start = g_off[node];

    const int grp = lane >> 3;
    const unsigned sub = lane & 7;
    const unsigned gmask = 0xFFu << (grp << 3);

    // src row held in registers for the whole bucket
    const f8 sa = ldg256(h + (size_t)node * ROWF + sub * 8);

    for (int chunk = 0; chunk < cnt; chunk += 32) {
        const int m = min(32, cnt - chunk);            // warp-uniform
        // coalesced pair fetch: lane l holds pair (chunk+l)
        int2 pr = make_int2(0, 0);
        if (lane < m) pr = g_pairs[start + chunk + lane];

        // iterate 4 edges per step (one per group); uniform loop bound
        int i0 = min(grp, m - 1);
        int d0   = __shfl_sync(0xFFFFFFFFu, pr.x, i0);
        int eid0 = __shfl_sync(0xFFFFFFFFu, pr.y, i0);
        f8 b = ldg256(h + (size_t)(unsigned)d0 * ROWF + sub * 8);

        for (int ii = 0; ii < m; ii += 4) {
            // issue next dst-row load before reducing current (pipeline)
            const bool have_next = (ii + 4 < m);       // warp-uniform
            int dn = 0, eidn = 0;
            f8 bn;
            if (have_next) {
                const int in = min(ii + 4 + grp, m - 1);
                dn   = __shfl_sync(0xFFFFFFFFu, pr.x, in);
                eidn = __shfl_sync(0xFFFFFFFFu, pr.y, in);
                bn = ldg256(h + (size_t)(unsigned)dn * ROWF + sub * 8);
            }

            float v = dot8(sa, b);
            v += __shfl_xor_sync(gmask, v, 4);
            v += __shfl_xor_sync(gmask, v, 2);
            v += __shfl_xor_sync(gmask, v, 1);

            if (ii + grp < m && sub == 0) out[eid0] = v;

            if (have_next) { b = bn; eid0 = eidn; }
        }
    }
}

// ---------------- fallback (R8 kernel) for unexpected sizes ----------------

__global__ __launch_bounds__(256)
void k_fallback(const float* __restrict__ h,
                const int* __restrict__ src,
                const int* __restrict__ dst,
                float* __restrict__ out,
                int n_edges)
{
    const int warp = threadIdx.x >> 5;
    const int lane = threadIdx.x & 31;
    const int grp  = lane >> 3;
    const unsigned sub = lane & 7;
    const unsigned gmask = 0xFFu << (grp << 3);

    const int e_base = (blockIdx.x * 8 + warp) * 8;
    if (e_base >= n_edges) return;
    const int nm1 = n_edges - 1;
    const int eA = min(e_base + grp, nm1);
    const int eB = min(e_base + 4 + grp, nm1);

    const unsigned sA = (unsigned)src[eA];
    const unsigned dA = (unsigned)dst[eA];
    const unsigned sB = (unsigned)src[eB];
    const unsigned dB = (unsigned)dst[eB];

    const f8 a = ldg256(h + (size_t)sA * ROWF + sub * 8);
    const f8 b = ldg256(h + (size_t)dA * ROWF + sub * 8);
    const f8 c = ldg256(h + (size_t)sB * ROWF + sub * 8);
    const f8 d = ldg256(h + (size_t)dB * ROWF + sub * 8);

    float vA = dot8(a, b);
    float vB = dot8(c, d);
    vA += __shfl_xor_sync(gmask, vA, 4);
    vB += __shfl_xor_sync(gmask, vB, 4);
    vA += __shfl_xor_sync(gmask, vA, 2);
    vB += __shfl_xor_sync(gmask, vB, 2);
    vA += __shfl_xor_sync(gmask, vA, 1);
    vB += __shfl_xor_sync(gmask, vB, 1);

    if (sub == 0) {
        if (e_base + grp     < n_edges) out[e_base + grp]     = vA;
        if (e_base + 4 + grp < n_edges) out[e_base + 4 + grp] = vB;
    }
}

extern "C" void kernel_launch(void* const* d_in, const int* in_sizes, int n_in,
                              void* d_out, int out_size)
{
    const float* h   = (const float*)d_in[0];
    const int*   src = (const int*)d_in[1];
    const int*   dst = (const int*)d_in[2];
    float*       out = (float*)d_out;

    const int n_edges = in_sizes[1];
    const int n_nodes = in_sizes[0] / ROWF;

    if (n_nodes > NCAP || n_edges > ECAP) {
        const int epb = 8 * 8;
        k_fallback<<<(n_edges + epb - 1) / epb, 256>>>(h, src, dst, out, n_edges);
        return;
    }

    const int nb_nodes = (n_nodes + 255) / 256;
    const int nb_edges = (n_edges + 255) / 256;

    k_zero<<<nb_nodes, 256>>>(n_nodes);
    k_hist<<<nb_edges, 256>>>(src, n_edges);
    k_alloc<<<nb_nodes, 256>>>(n_nodes);
    k_scatter<<<nb_edges, 256>>>(src, dst, n_edges);
    k_gather<<<(n_nodes + 7) / 8, 256>>>(h, out, n_nodes);
}

// round 13
// speedup vs baseline: 2.1997x; 2.1997x over previous
#include <cuda_runtime.h>
#include <cuda_bf16.h>
#include <cstdint>

// Per-edge dot product: score[e] = dot(h[src[e]], h[dst[e]]), D=64.
//
// 4-lanes-per-edge, 8 edges per warp in ONE pass:
//  - lane sub (0..3) of group grp loads 32B chunks #sub and #(sub+4) of each
//    256B row via ld.global.nc.v8.f32 (LDG.256). One warp instruction covers
//    half of 8 rows (1KB); 4 instructions gather all 8 edges' rows.
//  - reduction: 2-stage butterfly within 4 lanes (8 edges per SHFL instr).
//  - store: the 8 sub==0 lanes write 8 consecutive floats (1 wavefront).
//  - idx: 1 scalar LDG per src/dst covers all 8 edges (8 distinct addrs).
// vs R8: same gather wavefronts, ~25% fewer aux LSU/MIO instructions.

#define ROWF 64  // floats per row

struct f8 { float v0, v1, v2, v3, v4, v5, v6, v7; };

__device__ __forceinline__ f8 ldg256(const float* p) {
    f8 r;
    asm volatile("ld.global.nc.v8.f32 {%0,%1,%2,%3,%4,%5,%6,%7}, [%8];"
                 : "=f"(r.v0), "=f"(r.v1), "=f"(r.v2), "=f"(r.v3),
                   "=f"(r.v4), "=f"(r.v5), "=f"(r.v6), "=f"(r.v7)
                 : "l"(p));
    return r;
}

__device__ __forceinline__ float dot8(const f8& a, const f8& b) {
    float s0 = a.v0 * b.v0 + a.v1 * b.v1;
    float s1 = a.v2 * b.v2 + a.v3 * b.v3;
    float s2 = a.v4 * b.v4 + a.v5 * b.v5;
    float s3 = a.v6 * b.v6 + a.v7 * b.v7;
    return (s0 + s1) + (s2 + s3);
}

__global__ __launch_bounds__(256)
void u_dot_v_kernel(const float* __restrict__ h,
                    const int* __restrict__ src,
                    const int* __restrict__ dst,
                    float* __restrict__ out,
                    int n_edges)
{
    const int warp = threadIdx.x >> 5;
    const int lane = threadIdx.x & 31;
    const int grp  = lane >> 2;            // edge group within warp (0..7)
    const unsigned sub = lane & 3;         // lane within group
    const unsigned gmask = 0xFu << (grp << 2);

    // 8 edges per warp, one per 4-lane group
    const int e_base = (blockIdx.x * 8 + warp) * 8;
    if (e_base >= n_edges) return;

    if (e_base + 7 < n_edges) {
        // ---- fast path ----
        const int e = e_base + grp;
        const unsigned s = (unsigned)src[e];   // uniform within group
        const unsigned d = (unsigned)dst[e];

        const float* ps = h + (size_t)s * ROWF + sub * 8;
        const float* pd = h + (size_t)d * ROWF + sub * 8;

        // 4 LDG.256 in flight; each covers half of 8 rows (1KB)
        const f8 a0 = ldg256(ps);
        const f8 a1 = ldg256(ps + 32);
        const f8 b0 = ldg256(pd);
        const f8 b1 = ldg256(pd + 32);

        float v = dot8(a0, b0) + dot8(a1, b1);

        // 2-stage butterfly within each 4-lane group (8 edges per instr)
        v += __shfl_xor_sync(gmask, v, 2);
        v += __shfl_xor_sync(gmask, v, 1);

        // 8 lanes (sub==0) store 8 consecutive floats: 1 wavefront
        if (sub == 0) out[e] = v;
    } else {
        // ---- tail path: clamp index, guard store ----
        const int nm1 = n_edges - 1;
        const int e = e_base + grp;
        const int ec = e <= nm1 ? e : nm1;

        const unsigned s = (unsigned)src[ec];
        const unsigned d = (unsigned)dst[ec];

        const float* ps = h + (size_t)s * ROWF + sub * 8;
        const float* pd = h + (size_t)d * ROWF + sub * 8;

        const f8 a0 = ldg256(ps);
        const f8 a1 = ldg256(ps + 32);
        const f8 b0 = ldg256(pd);
        const f8 b1 = ldg256(pd + 32);

        float v = dot8(a0, b0) + dot8(a1, b1);

        v += __shfl_xor_sync(gmask, v, 2);
        v += __shfl_xor_sync(gmask, v, 1);

        if (sub == 0 && e < n_edges) out[e] = v;
    }
}

extern "C" void kernel_launch(void* const* d_in, const int* in_sizes, int n_in,
                              void* d_out, int out_size)
{
    const float* h   = (const float*)d_in[0];
    const int*   src = (const int*)d_in[1];
    const int*   dst = (const int*)d_in[2];
    float*       out = (float*)d_out;

    const int n_edges = in_sizes[1];
    const int edges_per_block = 8 * 8;   // 8 warps x 8 edges
    const int blocks = (n_edges + edges_per_block - 1) / edges_per_block;

    u_dot_v_kernel<<<blocks, 256>>>(h, src, dst, out, n_edges);
}